// round 16
// baseline (speedup 1.0000x reference)
#include <cuda_runtime.h>
#include <cuda_fp16.h>
#include <stdint.h>

// ---------------- problem constants ----------------
#define N_NODES 131072
#define F_DIM   512
#define HID     256
#define NGRAPH  512
#define NPG     256
#define KSEL    128
#define MARGIN  0.5f
#define LOSSW   0.2f

// ---------------- selection window (re-widened for fp16-accum jitter) ------
#define DEF_SEL  120
#define WIN      16
#define PICK     (KSEL - DEF_SEL)     // 8
#define NCAND    (NGRAPH * WIN)       // 8192

// ---------------- approx GEMM tiling (1-product fp16, fp16 accum) ----------
#define BM 128
#define KSTEP 32
#define NSTAGE (F_DIM/KSTEP)          // 16
#define ROWB 80
#define APX_A_TILE (BM*ROWB)
#define APX_B_TILE (HID*ROWB)
#define APX_SM_A   0
#define APX_SM_B   (2*APX_A_TILE)
#define APX_SM_B1  (APX_SM_B + 2*APX_B_TILE)
#define APX_SM_W2  (APX_SM_B1 + 1024)
#define APX_SM_PART (APX_SM_W2 + 1024)
#define APX_SMEM   (APX_SM_PART + 2048)       // 65536

// ---------------- refine tiling (R5/R8-proven: 64 cands x 128 cols) --------
#define RBM 64
#define RBN 128
#define RF_A_SPLIT (RBM*ROWB)
#define RF_B_SPLIT (RBN*ROWB)
#define RF_A_BUF   (2*RF_A_SPLIT)
#define RF_B_BUF   (2*RF_B_SPLIT)
#define RF_SM_A    0
#define RF_SM_B    (2*RF_A_BUF)
#define RF_SM_B1   (RF_SM_B + 2*RF_B_BUF)
#define RF_SM_W2   (RF_SM_B1 + 512)
#define RF_SM_PART (RF_SM_W2 + 512)
#define RF_SM_CAND (RF_SM_PART + 1024)
#define RF_SMEM    (RF_SM_CAND + 256)         // 63744
#define RF_GRID    (2 * (NCAND / RBM))        // 256

__device__ __half g_w1s[2][HID][F_DIM];
__device__ float g_scores[N_NODES];
__device__ int   g_cand[NCAND];
__device__ float g_candsc[NCAND];
__device__ float g_refine[2][NCAND];
__device__ float g_tot[NGRAPH];
__device__ float g_defsum[NGRAPH];
__device__ float g_pergraph[NGRAPH];

// ---------------- helpers ----------------
__device__ __forceinline__ uint32_t smem_u32(const void* p) {
    uint32_t a;
    asm("{ .reg .u64 t; cvta.to.shared.u64 t, %1; cvt.u32.u64 %0, t; }" : "=r"(a) : "l"(p));
    return a;
}
__device__ __forceinline__ void split2(float a, uint16_t& h0, uint16_t& h1) {
    __half p = __float2half_rn(a);
    float r = a - __half2float(p);
    __half q = __float2half_rn(r);
    h0 = __half_as_ushort(p);
    h1 = __half_as_ushort(q);
}

#define LDSM4(R, addr) \
    asm volatile("ldmatrix.sync.aligned.m8n8.x4.shared.b16 {%0,%1,%2,%3}, [%4];" \
        : "=r"((R)[0]), "=r"((R)[1]), "=r"((R)[2]), "=r"((R)[3]) : "r"(addr))

// fp32-accum MMA (refine path — exact numerics)
__device__ __forceinline__ void mma_fp16(float (&c)[4], const uint32_t (&a)[4],
                                         uint32_t b0, uint32_t b1) {
    asm volatile(
        "mma.sync.aligned.m16n8k16.row.col.f32.f16.f16.f32 "
        "{%0,%1,%2,%3}, {%4,%5,%6,%7}, {%8,%9}, {%0,%1,%2,%3};"
        : "+f"(c[0]), "+f"(c[1]), "+f"(c[2]), "+f"(c[3])
        : "r"(a[0]), "r"(a[1]), "r"(a[2]), "r"(a[3]), "r"(b0), "r"(b1));
}
// fp16-accum MMA (approx path — potentially double-rate)
__device__ __forceinline__ void mma_fp16h(uint32_t (&c)[2], const uint32_t (&a)[4],
                                          uint32_t b0, uint32_t b1) {
    asm volatile(
        "mma.sync.aligned.m16n8k16.row.col.f16.f16.f16.f16 "
        "{%0,%1}, {%2,%3,%4,%5}, {%6,%7}, {%0,%1};"
        : "+r"(c[0]), "+r"(c[1])
        : "r"(a[0]), "r"(a[1]), "r"(a[2]), "r"(a[3]), "r"(b0), "r"(b1));
}
__device__ __forceinline__ void cp16(uint32_t dst, const void* src) {
    asm volatile("cp.async.ca.shared.global [%0], [%1], 16;" :: "r"(dst), "l"(src) : "memory");
}

// ============================================================================
// Prep: W1 fp32 -> 2-way fp16 split, transposed to [split][n][k]
// ============================================================================
__global__ void prep_w1(const float* __restrict__ W1)
{
    int idx = blockIdx.x * 256 + threadIdx.x;
    int k = idx >> 8, n = idx & 255;
    uint16_t h0, h1;
    split2(W1[k * HID + n], h0, h1);
    g_w1s[0][n][k] = __ushort_as_half(h0);
    g_w1s[1][n][k] = __ushort_as_half(h1);
}

// ============================================================================
// Approx score GEMM with fp16 accumulators (half the accumulator registers,
// 2x HMMA rate if the fallback path matches prior-arch behavior).
// ============================================================================
__global__ __launch_bounds__(512, 1)
void approx_gemm(const float* __restrict__ x, const float* __restrict__ b1,
                 const float* __restrict__ W2, const float* __restrict__ b2)
{
    extern __shared__ char smem[];
    const uint32_t sb = smem_u32(smem);
    const int tid = threadIdx.x, wid = tid >> 5, lid = tid & 31;
    const int wm = wid >> 2, wn = wid & 3;
    const long long mbase = (long long)blockIdx.x * BM;

    if (tid < 256) {
        ((float*)(smem + APX_SM_B1))[tid] = b1[tid];
        ((float*)(smem + APX_SM_W2))[tid] = W2[tid];
    }

    const int a_lane = (lid & 15) * ROWB + ((lid >> 4) << 4);
    const int b_lane = ((lid & 7) + ((lid >> 4) << 3)) * ROWB + (((lid >> 3) & 1) << 4);

    const int xr = tid >> 2, xq = tid & 3;
    const int bn = tid >> 1, bh = tid & 1;

    uint32_t acc[2][8][2];
#pragma unroll
    for (int mt = 0; mt < 2; mt++)
#pragma unroll
        for (int nt = 0; nt < 8; nt++) { acc[mt][nt][0] = 0u; acc[mt][nt][1] = 0u; }

    const float* xrow = x + (mbase + xr) * F_DIM + xq * 8;

    auto stashA = [&](const float4& v0, const float4& v1, int bufsel) {
        __half2 h[4];
        h[0] = __float22half2_rn(make_float2(v0.x, v0.y));
        h[1] = __float22half2_rn(make_float2(v0.z, v0.w));
        h[2] = __float22half2_rn(make_float2(v1.x, v1.y));
        h[3] = __float22half2_rn(make_float2(v1.z, v1.w));
        *(uint4*)(smem + APX_SM_A + bufsel * APX_A_TILE + xr * ROWB + xq * 16) = *(uint4*)h;
    };
    auto fetchB = [&](int t, int bufsel) {
#pragma unroll
        for (int c = 0; c < 2; c++) {
            int chunk = bh * 2 + c;
            cp16(sb + APX_SM_B + bufsel * APX_B_TILE + bn * ROWB + chunk * 16,
                 &g_w1s[0][bn][t * KSTEP + chunk * 8]);
        }
    };

    float4 vx0 = *(const float4*)(xrow);
    float4 vx1 = *(const float4*)(xrow + 4);
    stashA(vx0, vx1, 0);
    fetchB(0, 0);
    asm volatile("cp.async.commit_group;" ::: "memory");

    for (int t = 0; t < NSTAGE; ++t) {
        const int buf = t & 1;
        if (t + 1 < NSTAGE) {
            vx0 = *(const float4*)(xrow + (t + 1) * KSTEP);
            vx1 = *(const float4*)(xrow + (t + 1) * KSTEP + 4);
            fetchB(t + 1, buf ^ 1);
            asm volatile("cp.async.commit_group;" ::: "memory");
            asm volatile("cp.async.wait_group 1;" ::: "memory");
        } else {
            asm volatile("cp.async.wait_group 0;" ::: "memory");
        }
        __syncthreads();

        const uint32_t ab = sb + APX_SM_A + buf * APX_A_TILE + wm * (32 * ROWB) + a_lane;
        const uint32_t bb = sb + APX_SM_B + buf * APX_B_TILE + wn * (64 * ROWB) + b_lane;
#pragma unroll
        for (int kh = 0; kh < 2; kh++) {
            uint32_t A0[4], A1[4], B0[4], B1[4], B2[4], B3[4];
            LDSM4(A0, ab + kh * 32);
            LDSM4(A1, ab + kh * 32 + 16 * ROWB);
            LDSM4(B0, bb + kh * 32);
            LDSM4(B1, bb + kh * 32 + 16 * ROWB);
            LDSM4(B2, bb + kh * 32 + 32 * ROWB);
            LDSM4(B3, bb + kh * 32 + 48 * ROWB);
#pragma unroll
            for (int mt = 0; mt < 2; mt++) {
                const uint32_t (&Am)[4] = (mt == 0) ? A0 : A1;
                mma_fp16h(acc[mt][0], Am, B0[0], B0[1]);
                mma_fp16h(acc[mt][1], Am, B0[2], B0[3]);
                mma_fp16h(acc[mt][2], Am, B1[0], B1[1]);
                mma_fp16h(acc[mt][3], Am, B1[2], B1[3]);
                mma_fp16h(acc[mt][4], Am, B2[0], B2[1]);
                mma_fp16h(acc[mt][5], Am, B2[2], B2[3]);
                mma_fp16h(acc[mt][6], Am, B3[0], B3[1]);
                mma_fp16h(acc[mt][7], Am, B3[2], B3[3]);
            }
        }
        if (t + 1 < NSTAGE) stashA(vx0, vx1, buf ^ 1);
        __syncthreads();
    }

    // epilogue: unpack fp16 accum -> fp32, relu(+b1).W2
    const float* smb1 = (const float*)(smem + APX_SM_B1);
    const float* smw2 = (const float*)(smem + APX_SM_W2);
    float* part = (float*)(smem + APX_SM_PART);
    const int grp = lid >> 2, tig = lid & 3;

#pragma unroll
    for (int mt = 0; mt < 2; mt++) {
        float p0 = 0.f, p1 = 0.f;
#pragma unroll
        for (int nt = 0; nt < 8; nt++) {
            float2 f0 = __half22float2(*(__half2*)&acc[mt][nt][0]);  // c0,c1 (row r)
            float2 f1 = __half22float2(*(__half2*)&acc[mt][nt][1]);  // c2,c3 (row r+8)
            const int c0 = wn * 64 + nt * 8 + tig * 2;
            const float b1a = smb1[c0],     w2a = smw2[c0];
            const float b1b = smb1[c0 + 1], w2b = smw2[c0 + 1];
            p0 += fmaxf(f0.x + b1a, 0.f) * w2a + fmaxf(f0.y + b1b, 0.f) * w2b;
            p1 += fmaxf(f1.x + b1a, 0.f) * w2a + fmaxf(f1.y + b1b, 0.f) * w2b;
        }
#pragma unroll
        for (int o = 1; o <= 2; o <<= 1) {
            p0 += __shfl_xor_sync(0xffffffffu, p0, o);
            p1 += __shfl_xor_sync(0xffffffffu, p1, o);
        }
        if (tig == 0) {
            part[wn * 128 + wm * 32 + mt * 16 + grp]     = p0;
            part[wn * 128 + wm * 32 + mt * 16 + grp + 8] = p1;
        }
    }
    __syncthreads();
    if (tid < 128) {
        float s = part[tid] + part[128 + tid] + part[256 + tid] + part[384 + tid];
        g_scores[mbase + tid] = s + b2[0];
    }
}

// ============================================================================
// FUSED topk + pool_def (R14 structure): one block per graph (512 threads).
// ============================================================================
__global__ __launch_bounds__(512)
void topk_pool_kernel(const float* __restrict__ x, float* __restrict__ out_mask,
                      float* __restrict__ out_pool)
{
    __shared__ float s[NPG];
    __shared__ float red[NPG];
    __shared__ float red2[NPG];
    __shared__ int   idxs[DEF_SEL];
    const int g = blockIdx.x, tid = threadIdx.x;

    if (tid < NPG) {
        const int j = tid;
        const float sj = g_scores[g * NPG + j];
        s[j] = sj;
        __syncthreads();

        int better = 0;
#pragma unroll 8
        for (int i = 0; i < NPG; i++) {
            float si = s[i];
            better += (si > sj) || (si == sj && i < j);
        }
        const bool def = better < DEF_SEL;
        out_mask[g * NPG + j] = def ? 1.0f : 0.0f;
        if (def) idxs[better] = j;
        if (better >= DEF_SEL && better < DEF_SEL + WIN) {
            int slot = g * WIN + (better - DEF_SEL);
            g_cand[slot]   = g * NPG + j;
            g_candsc[slot] = sj;
        }

        red[j]  = sj;
        red2[j] = def ? sj : 0.f;
        __syncthreads();
        for (int o = NPG / 2; o > 0; o >>= 1) {
            if (j < o) { red[j] += red[j + o]; red2[j] += red2[j + o]; }
            __syncthreads();
        }
        if (j == 0) { g_tot[g] = red[0]; g_defsum[g] = red2[0]; }
    } else {
        __syncthreads();
        __syncthreads();
        for (int o = NPG / 2; o > 0; o >>= 1) __syncthreads();
    }
    __syncthreads();

    // pool: all 512 threads, one fp32 column each; 120 = 15*8 exact
    const float* xg = x + (long long)g * NPG * F_DIM + tid;
    float a[8];
#pragma unroll
    for (int i = 0; i < 8; i++) a[i] = 0.f;
#pragma unroll 2
    for (int t = 0; t < DEF_SEL; t += 8) {
#pragma unroll
        for (int i = 0; i < 8; i++)
            a[i] += xg[idxs[t + i] * F_DIM];
    }
    out_pool[g * F_DIM + tid] =
        ((a[0] + a[1]) + (a[2] + a[3])) + ((a[4] + a[5]) + (a[6] + a[7]));
}

// ============================================================================
// Refine GEMM (R5/R8-proven shape): exact fp32-accum scores for 8192 cands.
// 256 CTAs: ct = bx & 127, nh = bx >> 7.
// ============================================================================
__global__ __launch_bounds__(256)
void refine_gemm(const float* __restrict__ x, const float* __restrict__ b1,
                 const float* __restrict__ W2)
{
    extern __shared__ char smem[];
    const uint32_t sb = smem_u32(smem);
    const int tid = threadIdx.x, wid = tid >> 5, lid = tid & 31;
    const int wm = wid >> 2, wn = wid & 3;
    const int ct = blockIdx.x & 127, nh = blockIdx.x >> 7;

    int* cand = (int*)(smem + RF_SM_CAND);
    if (tid < 64) cand[tid] = g_cand[ct * 64 + tid];
    if (tid < 128) {
        ((float*)(smem + RF_SM_B1))[tid] = b1[nh * 128 + tid];
        ((float*)(smem + RF_SM_W2))[tid] = W2[nh * 128 + tid];
    }
    __syncthreads();

    const int a_lane = (lid & 15) * ROWB + ((lid >> 4) << 4);
    const int b_lane = ((lid & 7) + ((lid >> 4) << 3)) * ROWB + (((lid >> 3) & 1) << 4);

    const int xr = tid >> 2, xq = tid & 3;
    const int bn = tid >> 1, bh = tid & 1;

    float acc[2][4][4];
#pragma unroll
    for (int mt = 0; mt < 2; mt++)
#pragma unroll
        for (int nt = 0; nt < 4; nt++)
#pragma unroll
            for (int i = 0; i < 4; i++) acc[mt][nt][i] = 0.f;

    const float* xrow = x + (long long)cand[xr] * F_DIM + xq * 8;

    auto stashA = [&](const float4& v0, const float4& v1, int bufsel) {
        uint16_t h0[8], h1[8];
        const float vf[8] = {v0.x, v0.y, v0.z, v0.w, v1.x, v1.y, v1.z, v1.w};
#pragma unroll
        for (int j = 0; j < 8; j++) split2(vf[j], h0[j], h1[j]);
        uint32_t off = RF_SM_A + bufsel * RF_A_BUF + xr * ROWB + xq * 16;
        *(uint4*)(smem + off)              = *(uint4*)h0;
        *(uint4*)(smem + off + RF_A_SPLIT) = *(uint4*)h1;
    };
    auto fetchB = [&](int t, int bufsel) {
#pragma unroll
        for (int s = 0; s < 2; s++)
#pragma unroll
            for (int c = 0; c < 2; c++) {
                int chunk = bh * 2 + c;
                cp16(sb + RF_SM_B + bufsel * RF_B_BUF + s * RF_B_SPLIT + bn * ROWB + chunk * 16,
                     &g_w1s[s][nh * 128 + bn][t * KSTEP + chunk * 8]);
            }
    };

    float4 vx0 = *(const float4*)(xrow);
    float4 vx1 = *(const float4*)(xrow + 4);
    stashA(vx0, vx1, 0);
    fetchB(0, 0);
    asm volatile("cp.async.commit_group;" ::: "memory");

    const int PA[3] = {0, 0, 1};
    const int PB[3] = {0, 1, 0};

    for (int t = 0; t < NSTAGE; ++t) {
        const int buf = t & 1;
        if (t + 1 < NSTAGE) {
            vx0 = *(const float4*)(xrow + (t + 1) * KSTEP);
            vx1 = *(const float4*)(xrow + (t + 1) * KSTEP + 4);
            fetchB(t + 1, buf ^ 1);
            asm volatile("cp.async.commit_group;" ::: "memory");
            asm volatile("cp.async.wait_group 1;" ::: "memory");
        } else {
            asm volatile("cp.async.wait_group 0;" ::: "memory");
        }
        __syncthreads();

        const uint32_t abase = sb + RF_SM_A + buf * RF_A_BUF + wm * (32 * ROWB) + a_lane;
        const uint32_t bbase = sb + RF_SM_B + buf * RF_B_BUF + wn * (32 * ROWB) + b_lane;
#pragma unroll
        for (int p = 0; p < 3; p++) {
            const uint32_t ab = abase + PA[p] * RF_A_SPLIT;
            const uint32_t bb = bbase + PB[p] * RF_B_SPLIT;
#pragma unroll
            for (int kh = 0; kh < 2; kh++) {
                uint32_t A0[4], A1[4], B0[4], B1[4];
                LDSM4(A0, ab + kh * 32);
                LDSM4(A1, ab + kh * 32 + 16 * ROWB);
                LDSM4(B0, bb + kh * 32);
                LDSM4(B1, bb + kh * 32 + 16 * ROWB);
#pragma unroll
                for (int mt = 0; mt < 2; mt++) {
                    const uint32_t (&Am)[4] = (mt == 0) ? A0 : A1;
                    mma_fp16(acc[mt][0], Am, B0[0], B0[1]);
                    mma_fp16(acc[mt][1], Am, B0[2], B0[3]);
                    mma_fp16(acc[mt][2], Am, B1[0], B1[1]);
                    mma_fp16(acc[mt][3], Am, B1[2], B1[3]);
                }
            }
        }
        if (t + 1 < NSTAGE) stashA(vx0, vx1, buf ^ 1);
        __syncthreads();
    }

    const float* smb1 = (const float*)(smem + RF_SM_B1);
    const float* smw2 = (const float*)(smem + RF_SM_W2);
    float* part = (float*)(smem + RF_SM_PART);
    const int grp = lid >> 2, tig = lid & 3;

#pragma unroll
    for (int mt = 0; mt < 2; mt++) {
        float p0 = 0.f, p1 = 0.f;
#pragma unroll
        for (int nt = 0; nt < 4; nt++) {
            const int c0 = wn * 32 + nt * 8 + tig * 2;
            const float b1a = smb1[c0],     w2a = smw2[c0];
            const float b1b = smb1[c0 + 1], w2b = smw2[c0 + 1];
            p0 += fmaxf(acc[mt][nt][0] + b1a, 0.f) * w2a
                + fmaxf(acc[mt][nt][1] + b1b, 0.f) * w2b;
            p1 += fmaxf(acc[mt][nt][2] + b1a, 0.f) * w2a
                + fmaxf(acc[mt][nt][3] + b1b, 0.f) * w2b;
        }
#pragma unroll
        for (int o = 1; o <= 2; o <<= 1) {
            p0 += __shfl_xor_sync(0xffffffffu, p0, o);
            p1 += __shfl_xor_sync(0xffffffffu, p1, o);
        }
        if (tig == 0) {
            part[wn * 64 + wm * 32 + mt * 16 + grp]     = p0;
            part[wn * 64 + wm * 32 + mt * 16 + grp + 8] = p1;
        }
    }
    __syncthreads();
    if (tid < 64) {
        float s = part[tid] + part[64 + tid] + part[128 + tid] + part[192 + tid];
        g_refine[nh][ct * 64 + tid] = s;
    }
}

// ============================================================================
// FUSED select + pool_fix: warp 0 picks PICK winners of WIN + loss term;
// all 512 threads add the winner rows.
// ============================================================================
__global__ __launch_bounds__(512)
void selectfix_kernel(const float* __restrict__ x, float* __restrict__ out_mask,
                      float* __restrict__ out_pool)
{
    __shared__ float sc[WIN];
    __shared__ int   id[WIN];
    __shared__ int   winners[PICK];
    const int g = blockIdx.x, tid = threadIdx.x;

    if (tid < 32) {
        const int c = tid;
        if (c < WIN) {
            int slot = g * WIN + c;
            sc[c] = g_refine[0][slot] + g_refine[1][slot];
            id[c] = g_cand[slot];
        }
        __syncwarp();

        float wsum = 0.f;
        if (c < WIN) {
            float scv = sc[c];
            int me = id[c], better = 0;
#pragma unroll
            for (int j = 0; j < WIN; j++) {
                float t = sc[j];
                better += (t > scv) || (t == scv && id[j] < me);
            }
            if (better < PICK) {
                out_mask[me] = 1.0f;
                winners[better] = me;
                wsum = g_candsc[g * WIN + c];
            }
        }
#pragma unroll
        for (int o = 16; o > 0; o >>= 1)
            wsum += __shfl_xor_sync(0xffffffffu, wsum, o);

        if (c == 0) {
            float selsum  = g_defsum[g] + wsum;
            float tot     = g_tot[g];
            float selmean = selsum / (float)KSEL;
            float unsmean = (tot - selsum) / (float)(NPG - KSEL);
            g_pergraph[g] = fmaxf(0.f, MARGIN - (selmean - unsmean));
        }
    }
    __syncthreads();

    float s = out_pool[g * F_DIM + tid];
#pragma unroll
    for (int i = 0; i < PICK; i++)
        s += x[(long long)winners[i] * F_DIM + tid];
    out_pool[g * F_DIM + tid] = s;
}

// ============================================================================
// loss: fixed-order reduction (deterministic)
// ============================================================================
__global__ void loss_kernel(float* __restrict__ out_loss)
{
    __shared__ float red[NGRAPH];
    const int j = threadIdx.x;
    red[j] = g_pergraph[j];
    __syncthreads();
    for (int o = NGRAPH / 2; o > 0; o >>= 1) {
        if (j < o) red[j] += red[j + o];
        __syncthreads();
    }
    if (j == 0) out_loss[0] = red[0] * (LOSSW / (float)NGRAPH);
}

// ============================================================================
// out = [ x_pooled (512*512) | topk_loss (1) | selected_mask (131072) ]
// DAG: prep -> approx(fp16-accum) -> topk+pool -> refine(WIN=16) ->
//      select+fix -> loss
// ============================================================================
extern "C" void kernel_launch(void* const* d_in, const int* in_sizes, int n_in,
                              void* d_out, int out_size)
{
    const float* x  = (const float*)d_in[0];
    const float* W1 = (const float*)d_in[2];
    const float* b1 = (const float*)d_in[3];
    const float* W2 = (const float*)d_in[4];
    const float* b2 = (const float*)d_in[5];

    float* out      = (float*)d_out;
    float* out_pool = out;
    float* out_loss = out + NGRAPH * F_DIM;
    float* out_mask = out + NGRAPH * F_DIM + 1;

    static bool attrs_set = false;
    if (!attrs_set) {
        cudaFuncSetAttribute(approx_gemm, cudaFuncAttributeMaxDynamicSharedMemorySize, APX_SMEM);
        cudaFuncSetAttribute(refine_gemm, cudaFuncAttributeMaxDynamicSharedMemorySize, RF_SMEM);
        attrs_set = true;
    }

    prep_w1<<<512, 256>>>(W1);
    approx_gemm<<<N_NODES / BM, 512, APX_SMEM>>>(x, b1, W2, b2);
    topk_pool_kernel<<<NGRAPH, 512>>>(x, out_mask, out_pool);
    refine_gemm<<<RF_GRID, 256, RF_SMEM>>>(x, b1, W2);
    selectfix_kernel<<<NGRAPH, 512>>>(x, out_mask, out_pool);
    loss_kernel<<<1, NGRAPH>>>(out_loss);
}

// round 17
// speedup vs baseline: 1.0752x; 1.0752x over previous
#include <cuda_runtime.h>
#include <cuda_fp16.h>
#include <stdint.h>

// ---------------- problem constants ----------------
#define N_NODES 131072
#define F_DIM   512
#define HID     256
#define NGRAPH  512
#define NPG     256
#define KSEL    128
#define MARGIN  0.5f
#define LOSSW   0.2f

// ---------------- selection window ----------------
#define DEF_SEL  124
#define WIN      8
#define PICK     (KSEL - DEF_SEL)     // 4
#define NCAND    (NGRAPH * WIN)       // 4096

// ---------------- approx GEMM tiling (1-product fp16, fp32 accum) ----------
#define BM 128
#define KSTEP 32
#define NSTAGE (F_DIM/KSTEP)          // 16
#define ROWB 80
#define APX_A_TILE (BM*ROWB)
#define APX_B_TILE (HID*ROWB)
#define APX_SM_A   0
#define APX_SM_B   (2*APX_A_TILE)
#define APX_SM_B1  (APX_SM_B + 2*APX_B_TILE)
#define APX_SM_W2  (APX_SM_B1 + 1024)
#define APX_SM_PART (APX_SM_W2 + 1024)
#define APX_SMEM   (APX_SM_PART + 2048)       // 65536

// ---------------- refine tiling (R8-proven: 64 cands x 128 cols) ----------
#define RBM 64
#define RBN 128
#define RF_A_SPLIT (RBM*ROWB)
#define RF_B_SPLIT (RBN*ROWB)
#define RF_A_BUF   (2*RF_A_SPLIT)
#define RF_B_BUF   (2*RF_B_SPLIT)
#define RF_SM_A    0
#define RF_SM_B    (2*RF_A_BUF)
#define RF_SM_B1   (RF_SM_B + 2*RF_B_BUF)
#define RF_SM_W2   (RF_SM_B1 + 512)
#define RF_SM_PART (RF_SM_W2 + 512)
#define RF_SM_CAND (RF_SM_PART + 1024)
#define RF_SMEM    (RF_SM_CAND + 256)         // 63744
#define RF_GRID    (2 * (NCAND / RBM))        // 128

__device__ __half g_w1s[2][HID][F_DIM];
__device__ float g_scores[N_NODES];
__device__ int   g_cand[NCAND];
__device__ float g_refine[2][NCAND];
__device__ float g_tot[NGRAPH];
__device__ float g_defsum[NGRAPH];
__device__ float g_pergraph[NGRAPH];

// ---------------- helpers ----------------
__device__ __forceinline__ uint32_t smem_u32(const void* p) {
    uint32_t a;
    asm("{ .reg .u64 t; cvta.to.shared.u64 t, %1; cvt.u32.u64 %0, t; }" : "=r"(a) : "l"(p));
    return a;
}
__device__ __forceinline__ void split2(float a, uint16_t& h0, uint16_t& h1) {
    __half p = __float2half_rn(a);
    float r = a - __half2float(p);
    __half q = __float2half_rn(r);
    h0 = __half_as_ushort(p);
    h1 = __half_as_ushort(q);
}

#define LDSM4(R, addr) \
    asm volatile("ldmatrix.sync.aligned.m8n8.x4.shared.b16 {%0,%1,%2,%3}, [%4];" \
        : "=r"((R)[0]), "=r"((R)[1]), "=r"((R)[2]), "=r"((R)[3]) : "r"(addr))

__device__ __forceinline__ void mma_fp16(float (&c)[4], const uint32_t (&a)[4],
                                         uint32_t b0, uint32_t b1) {
    asm volatile(
        "mma.sync.aligned.m16n8k16.row.col.f32.f16.f16.f32 "
        "{%0,%1,%2,%3}, {%4,%5,%6,%7}, {%8,%9}, {%0,%1,%2,%3};"
        : "+f"(c[0]), "+f"(c[1]), "+f"(c[2]), "+f"(c[3])
        : "r"(a[0]), "r"(a[1]), "r"(a[2]), "r"(a[3]), "r"(b0), "r"(b1));
}
__device__ __forceinline__ void cp16(uint32_t dst, const void* src) {
    asm volatile("cp.async.ca.shared.global [%0], [%1], 16;" :: "r"(dst), "l"(src) : "memory");
}

// ============================================================================
// Prep: W1 fp32 -> 2-way fp16 split, transposed to [split][n][k]
// ============================================================================
__global__ void prep_w1(const float* __restrict__ W1)
{
    int idx = blockIdx.x * 256 + threadIdx.x;
    int k = idx >> 8, n = idx & 255;
    uint16_t h0, h1;
    split2(W1[k * HID + n], h0, h1);
    g_w1s[0][n][k] = __ushort_as_half(h0);
    g_w1s[1][n][k] = __ushort_as_half(h1);
}

// ============================================================================
// Approx score GEMM (fp32 accum — at the fallback-HMMA issue ceiling)
// ============================================================================
__global__ __launch_bounds__(512, 1)
void approx_gemm(const float* __restrict__ x, const float* __restrict__ b1,
                 const float* __restrict__ W2, const float* __restrict__ b2)
{
    extern __shared__ char smem[];
    const uint32_t sb = smem_u32(smem);
    const int tid = threadIdx.x, wid = tid >> 5, lid = tid & 31;
    const int wm = wid >> 2, wn = wid & 3;
    const long long mbase = (long long)blockIdx.x * BM;

    if (tid < 256) {
        ((float*)(smem + APX_SM_B1))[tid] = b1[tid];
        ((float*)(smem + APX_SM_W2))[tid] = W2[tid];
    }

    const int a_lane = (lid & 15) * ROWB + ((lid >> 4) << 4);
    const int b_lane = ((lid & 7) + ((lid >> 4) << 3)) * ROWB + (((lid >> 3) & 1) << 4);

    const int xr = tid >> 2, xq = tid & 3;
    const int bn = tid >> 1, bh = tid & 1;

    float acc[2][8][4];
#pragma unroll
    for (int mt = 0; mt < 2; mt++)
#pragma unroll
        for (int nt = 0; nt < 8; nt++)
#pragma unroll
            for (int i = 0; i < 4; i++) acc[mt][nt][i] = 0.f;

    const float* xrow = x + (mbase + xr) * F_DIM + xq * 8;

    auto stashA = [&](const float4& v0, const float4& v1, int bufsel) {
        __half2 h[4];
        h[0] = __float22half2_rn(make_float2(v0.x, v0.y));
        h[1] = __float22half2_rn(make_float2(v0.z, v0.w));
        h[2] = __float22half2_rn(make_float2(v1.x, v1.y));
        h[3] = __float22half2_rn(make_float2(v1.z, v1.w));
        *(uint4*)(smem + APX_SM_A + bufsel * APX_A_TILE + xr * ROWB + xq * 16) = *(uint4*)h;
    };
    auto fetchB = [&](int t, int bufsel) {
#pragma unroll
        for (int c = 0; c < 2; c++) {
            int chunk = bh * 2 + c;
            cp16(sb + APX_SM_B + bufsel * APX_B_TILE + bn * ROWB + chunk * 16,
                 &g_w1s[0][bn][t * KSTEP + chunk * 8]);
        }
    };

    float4 vx0 = *(const float4*)(xrow);
    float4 vx1 = *(const float4*)(xrow + 4);
    stashA(vx0, vx1, 0);
    fetchB(0, 0);
    asm volatile("cp.async.commit_group;" ::: "memory");

    for (int t = 0; t < NSTAGE; ++t) {
        const int buf = t & 1;
        if (t + 1 < NSTAGE) {
            vx0 = *(const float4*)(xrow + (t + 1) * KSTEP);
            vx1 = *(const float4*)(xrow + (t + 1) * KSTEP + 4);
            fetchB(t + 1, buf ^ 1);
            asm volatile("cp.async.commit_group;" ::: "memory");
            asm volatile("cp.async.wait_group 1;" ::: "memory");
        } else {
            asm volatile("cp.async.wait_group 0;" ::: "memory");
        }
        __syncthreads();

        const uint32_t ab = sb + APX_SM_A + buf * APX_A_TILE + wm * (32 * ROWB) + a_lane;
        const uint32_t bb = sb + APX_SM_B + buf * APX_B_TILE + wn * (64 * ROWB) + b_lane;
#pragma unroll
        for (int kh = 0; kh < 2; kh++) {
            uint32_t A0[4], A1[4], B0[4], B1[4], B2[4], B3[4];
            LDSM4(A0, ab + kh * 32);
            LDSM4(A1, ab + kh * 32 + 16 * ROWB);
            LDSM4(B0, bb + kh * 32);
            LDSM4(B1, bb + kh * 32 + 16 * ROWB);
            LDSM4(B2, bb + kh * 32 + 32 * ROWB);
            LDSM4(B3, bb + kh * 32 + 48 * ROWB);
#pragma unroll
            for (int mt = 0; mt < 2; mt++) {
                const uint32_t (&Am)[4] = (mt == 0) ? A0 : A1;
                mma_fp16(acc[mt][0], Am, B0[0], B0[1]);
                mma_fp16(acc[mt][1], Am, B0[2], B0[3]);
                mma_fp16(acc[mt][2], Am, B1[0], B1[1]);
                mma_fp16(acc[mt][3], Am, B1[2], B1[3]);
                mma_fp16(acc[mt][4], Am, B2[0], B2[1]);
                mma_fp16(acc[mt][5], Am, B2[2], B2[3]);
                mma_fp16(acc[mt][6], Am, B3[0], B3[1]);
                mma_fp16(acc[mt][7], Am, B3[2], B3[3]);
            }
        }
        if (t + 1 < NSTAGE) stashA(vx0, vx1, buf ^ 1);
        __syncthreads();
    }

    const float* smb1 = (const float*)(smem + APX_SM_B1);
    const float* smw2 = (const float*)(smem + APX_SM_W2);
    float* part = (float*)(smem + APX_SM_PART);
    const int grp = lid >> 2, tig = lid & 3;

#pragma unroll
    for (int mt = 0; mt < 2; mt++) {
        float p0 = 0.f, p1 = 0.f;
#pragma unroll
        for (int nt = 0; nt < 8; nt++) {
            const int c0 = wn * 64 + nt * 8 + tig * 2;
            const float b1a = smb1[c0],     w2a = smw2[c0];
            const float b1b = smb1[c0 + 1], w2b = smw2[c0 + 1];
            p0 += fmaxf(acc[mt][nt][0] + b1a, 0.f) * w2a
                + fmaxf(acc[mt][nt][1] + b1b, 0.f) * w2b;
            p1 += fmaxf(acc[mt][nt][2] + b1a, 0.f) * w2a
                + fmaxf(acc[mt][nt][3] + b1b, 0.f) * w2b;
        }
#pragma unroll
        for (int o = 1; o <= 2; o <<= 1) {
            p0 += __shfl_xor_sync(0xffffffffu, p0, o);
            p1 += __shfl_xor_sync(0xffffffffu, p1, o);
        }
        if (tig == 0) {
            part[wn * 128 + wm * 32 + mt * 16 + grp]     = p0;
            part[wn * 128 + wm * 32 + mt * 16 + grp + 8] = p1;
        }
    }
    __syncthreads();
    if (tid < 128) {
        float s = part[tid] + part[128 + tid] + part[256 + tid] + part[384 + tid];
        g_scores[mbase + tid] = s + b2[0];
    }
}

// ============================================================================
// FUSED topk + pool_def: one block per graph (512 threads).
// ============================================================================
__global__ __launch_bounds__(512)
void topk_pool_kernel(const float* __restrict__ x, float* __restrict__ out_mask,
                      float* __restrict__ out_pool)
{
    __shared__ float s[NPG];
    __shared__ float red[NPG];
    __shared__ float red2[NPG];
    __shared__ int   idxs[DEF_SEL];
    const int g = blockIdx.x, tid = threadIdx.x;

    if (tid < NPG) {
        const int j = tid;
        const float sj = g_scores[g * NPG + j];
        s[j] = sj;
        __syncthreads();

        int better = 0;
#pragma unroll 8
        for (int i = 0; i < NPG; i++) {
            float si = s[i];
            better += (si > sj) || (si == sj && i < j);
        }
        const bool def = better < DEF_SEL;
        out_mask[g * NPG + j] = def ? 1.0f : 0.0f;
        if (def) idxs[better] = j;
        if (better >= DEF_SEL && better < DEF_SEL + WIN)
            g_cand[g * WIN + (better - DEF_SEL)] = g * NPG + j;

        red[j]  = sj;
        red2[j] = def ? sj : 0.f;
        __syncthreads();
        for (int o = NPG / 2; o > 0; o >>= 1) {
            if (j < o) { red[j] += red[j + o]; red2[j] += red2[j + o]; }
            __syncthreads();
        }
        if (j == 0) { g_tot[g] = red[0]; g_defsum[g] = red2[0]; }
    } else {
        __syncthreads();
        __syncthreads();
        for (int o = NPG / 2; o > 0; o >>= 1) __syncthreads();
    }
    __syncthreads();

    const float* xg = x + (long long)g * NPG * F_DIM + tid;
    float a[8];
#pragma unroll
    for (int i = 0; i < 8; i++) a[i] = 0.f;
    int t = 0;
#pragma unroll 2
    for (; t + 8 <= DEF_SEL; t += 8) {           // 120 = 15*8
#pragma unroll
        for (int i = 0; i < 8; i++)
            a[i] += xg[idxs[t + i] * F_DIM];
    }
#pragma unroll
    for (int i = 0; i < 4; i++)                  // remainder 4
        a[i] += xg[idxs[t + i] * F_DIM];
    out_pool[g * F_DIM + tid] =
        ((a[0] + a[1]) + (a[2] + a[3])) + ((a[4] + a[5]) + (a[6] + a[7]));
}

// ============================================================================
// Refine GEMM (R8-proven): exact fp32-accum scores for 4096 candidates.
// ============================================================================
__global__ __launch_bounds__(256)
void refine_gemm(const float* __restrict__ x, const float* __restrict__ b1,
                 const float* __restrict__ W2)
{
    extern __shared__ char smem[];
    const uint32_t sb = smem_u32(smem);
    const int tid = threadIdx.x, wid = tid >> 5, lid = tid & 31;
    const int wm = wid >> 2, wn = wid & 3;
    const int ct = blockIdx.x & 63, nh = blockIdx.x >> 6;

    int* cand = (int*)(smem + RF_SM_CAND);
    if (tid < 64) cand[tid] = g_cand[ct * 64 + tid];
    if (tid < 128) {
        ((float*)(smem + RF_SM_B1))[tid] = b1[nh * 128 + tid];
        ((float*)(smem + RF_SM_W2))[tid] = W2[nh * 128 + tid];
    }
    __syncthreads();

    const int a_lane = (lid & 15) * ROWB + ((lid >> 4) << 4);
    const int b_lane = ((lid & 7) + ((lid >> 4) << 3)) * ROWB + (((lid >> 3) & 1) << 4);

    const int xr = tid >> 2, xq = tid & 3;
    const int bn = tid >> 1, bh = tid & 1;

    float acc[2][4][4];
#pragma unroll
    for (int mt = 0; mt < 2; mt++)
#pragma unroll
        for (int nt = 0; nt < 4; nt++)
#pragma unroll
            for (int i = 0; i < 4; i++) acc[mt][nt][i] = 0.f;

    const float* xrow = x + (long long)cand[xr] * F_DIM + xq * 8;

    auto stashA = [&](const float4& v0, const float4& v1, int bufsel) {
        uint16_t h0[8], h1[8];
        const float vf[8] = {v0.x, v0.y, v0.z, v0.w, v1.x, v1.y, v1.z, v1.w};
#pragma unroll
        for (int j = 0; j < 8; j++) split2(vf[j], h0[j], h1[j]);
        uint32_t off = RF_SM_A + bufsel * RF_A_BUF + xr * ROWB + xq * 16;
        *(uint4*)(smem + off)              = *(uint4*)h0;
        *(uint4*)(smem + off + RF_A_SPLIT) = *(uint4*)h1;
    };
    auto fetchB = [&](int t, int bufsel) {
#pragma unroll
        for (int s = 0; s < 2; s++)
#pragma unroll
            for (int c = 0; c < 2; c++) {
                int chunk = bh * 2 + c;
                cp16(sb + RF_SM_B + bufsel * RF_B_BUF + s * RF_B_SPLIT + bn * ROWB + chunk * 16,
                     &g_w1s[s][nh * 128 + bn][t * KSTEP + chunk * 8]);
            }
    };

    float4 vx0 = *(const float4*)(xrow);
    float4 vx1 = *(const float4*)(xrow + 4);
    stashA(vx0, vx1, 0);
    fetchB(0, 0);
    asm volatile("cp.async.commit_group;" ::: "memory");

    const int PA[3] = {0, 0, 1};
    const int PB[3] = {0, 1, 0};

    for (int t = 0; t < NSTAGE; ++t) {
        const int buf = t & 1;
        if (t + 1 < NSTAGE) {
            vx0 = *(const float4*)(xrow + (t + 1) * KSTEP);
            vx1 = *(const float4*)(xrow + (t + 1) * KSTEP + 4);
            fetchB(t + 1, buf ^ 1);
            asm volatile("cp.async.commit_group;" ::: "memory");
            asm volatile("cp.async.wait_group 1;" ::: "memory");
        } else {
            asm volatile("cp.async.wait_group 0;" ::: "memory");
        }
        __syncthreads();

        const uint32_t abase = sb + RF_SM_A + buf * RF_A_BUF + wm * (32 * ROWB) + a_lane;
        const uint32_t bbase = sb + RF_SM_B + buf * RF_B_BUF + wn * (32 * ROWB) + b_lane;
#pragma unroll
        for (int p = 0; p < 3; p++) {
            const uint32_t ab = abase + PA[p] * RF_A_SPLIT;
            const uint32_t bb = bbase + PB[p] * RF_B_SPLIT;
#pragma unroll
            for (int kh = 0; kh < 2; kh++) {
                uint32_t A0[4], A1[4], B0[4], B1[4];
                LDSM4(A0, ab + kh * 32);
                LDSM4(A1, ab + kh * 32 + 16 * ROWB);
                LDSM4(B0, bb + kh * 32);
                LDSM4(B1, bb + kh * 32 + 16 * ROWB);
#pragma unroll
                for (int mt = 0; mt < 2; mt++) {
                    const uint32_t (&Am)[4] = (mt == 0) ? A0 : A1;
                    mma_fp16(acc[mt][0], Am, B0[0], B0[1]);
                    mma_fp16(acc[mt][1], Am, B0[2], B0[3]);
                    mma_fp16(acc[mt][2], Am, B1[0], B1[1]);
                    mma_fp16(acc[mt][3], Am, B1[2], B1[3]);
                }
            }
        }
        if (t + 1 < NSTAGE) stashA(vx0, vx1, buf ^ 1);
        __syncthreads();
    }

    const float* smb1 = (const float*)(smem + RF_SM_B1);
    const float* smw2 = (const float*)(smem + RF_SM_W2);
    float* part = (float*)(smem + RF_SM_PART);
    const int grp = lid >> 2, tig = lid & 3;

#pragma unroll
    for (int mt = 0; mt < 2; mt++) {
        float p0 = 0.f, p1 = 0.f;
#pragma unroll
        for (int nt = 0; nt < 4; nt++) {
            const int c0 = wn * 32 + nt * 8 + tig * 2;
            const float b1a = smb1[c0],     w2a = smw2[c0];
            const float b1b = smb1[c0 + 1], w2b = smw2[c0 + 1];
            p0 += fmaxf(acc[mt][nt][0] + b1a, 0.f) * w2a
                + fmaxf(acc[mt][nt][1] + b1b, 0.f) * w2b;
            p1 += fmaxf(acc[mt][nt][2] + b1a, 0.f) * w2a
                + fmaxf(acc[mt][nt][3] + b1b, 0.f) * w2b;
        }
#pragma unroll
        for (int o = 1; o <= 2; o <<= 1) {
            p0 += __shfl_xor_sync(0xffffffffu, p0, o);
            p1 += __shfl_xor_sync(0xffffffffu, p1, o);
        }
        if (tig == 0) {
            part[wn * 64 + wm * 32 + mt * 16 + grp]     = p0;
            part[wn * 64 + wm * 32 + mt * 16 + grp + 8] = p1;
        }
    }
    __syncthreads();
    if (tid < 64) {
        float s = part[tid] + part[64 + tid] + part[128 + tid] + part[192 + tid];
        g_refine[nh][ct * 64 + tid] = s;
    }
}

// ============================================================================
// FUSED select + pool_fix
// ============================================================================
__global__ __launch_bounds__(512)
void selectfix_kernel(const float* __restrict__ x, float* __restrict__ out_mask,
                      float* __restrict__ out_pool)
{
    __shared__ float sc[WIN];
    __shared__ int   id[WIN];
    __shared__ int   winners[PICK];
    const int g = blockIdx.x, tid = threadIdx.x;

    if (tid < 32) {
        const int c = tid;
        if (c < WIN) {
            int slot = g * WIN + c;
            sc[c] = g_refine[0][slot] + g_refine[1][slot];
            id[c] = g_cand[slot];
        }
        __syncwarp();

        float wsum = 0.f;
        if (c < WIN) {
            float scv = sc[c];
            int me = id[c], better = 0;
#pragma unroll
            for (int j = 0; j < WIN; j++) {
                float t = sc[j];
                better += (t > scv) || (t == scv && id[j] < me);
            }
            if (better < PICK) {
                out_mask[me] = 1.0f;
                winners[better] = me;
                wsum = g_scores[me];
            }
        }
#pragma unroll
        for (int o = 16; o > 0; o >>= 1)
            wsum += __shfl_xor_sync(0xffffffffu, wsum, o);

        if (c == 0) {
            float selsum  = g_defsum[g] + wsum;
            float tot     = g_tot[g];
            float selmean = selsum / (float)KSEL;
            float unsmean = (tot - selsum) / (float)(NPG - KSEL);
            g_pergraph[g] = fmaxf(0.f, MARGIN - (selmean - unsmean));
        }
    }
    __syncthreads();

    float s = out_pool[g * F_DIM + tid];
#pragma unroll
    for (int i = 0; i < PICK; i++)
        s += x[(long long)winners[i] * F_DIM + tid];
    out_pool[g * F_DIM + tid] = s;
}

// ============================================================================
// loss: fixed-order reduction (deterministic)
// ============================================================================
__global__ void loss_kernel(float* __restrict__ out_loss)
{
    __shared__ float red[NGRAPH];
    const int j = threadIdx.x;
    red[j] = g_pergraph[j];
    __syncthreads();
    for (int o = NGRAPH / 2; o > 0; o >>= 1) {
        if (j < o) red[j] += red[j + o];
        __syncthreads();
    }
    if (j == 0) out_loss[0] = red[0] * (LOSSW / (float)NGRAPH);
}

// ============================================================================
// out = [ x_pooled (512*512) | topk_loss (1) | selected_mask (131072) ]
// DAG: prep -> approx -> topk+pool -> refine -> select+fix -> loss
// ============================================================================
extern "C" void kernel_launch(void* const* d_in, const int* in_sizes, int n_in,
                              void* d_out, int out_size)
{
    const float* x  = (const float*)d_in[0];
    const float* W1 = (const float*)d_in[2];
    const float* b1 = (const float*)d_in[3];
    const float* W2 = (const float*)d_in[4];
    const float* b2 = (const float*)d_in[5];

    float* out      = (float*)d_out;
    float* out_pool = out;
    float* out_loss = out + NGRAPH * F_DIM;
    float* out_mask = out + NGRAPH * F_DIM + 1;

    static bool attrs_set = false;
    if (!attrs_set) {
        cudaFuncSetAttribute(approx_gemm, cudaFuncAttributeMaxDynamicSharedMemorySize, APX_SMEM);
        cudaFuncSetAttribute(refine_gemm, cudaFuncAttributeMaxDynamicSharedMemorySize, RF_SMEM);
        attrs_set = true;
    }

    prep_w1<<<512, 256>>>(W1);
    approx_gemm<<<N_NODES / BM, 512, APX_SMEM>>>(x, b1, W2, b2);
    topk_pool_kernel<<<NGRAPH, 512>>>(x, out_mask, out_pool);
    refine_gemm<<<RF_GRID, 256, RF_SMEM>>>(x, b1, W2);
    selectfix_kernel<<<NGRAPH, 512>>>(x, out_mask, out_pool);
    loss_kernel<<<1, NGRAPH>>>(out_loss);
}